// round 10
// baseline (speedup 1.0000x reference)
#include <cuda_runtime.h>
#include <cstdint>

// PSRoIAlign: feat [B=4, C=784, H=80, W=80] fp32, rois [512,5] fp32
// out [512, 16, 7, 7] fp32.  Channel index == intra-ROI output index.
//
// R7: co-amortization.  All 16 co-channels of a bin (n,i,j) share rows,
// columns, bilinear weights and window selectors -- only the plane base
// differs by a constant stride (49 planes = 1.2544 MB per co step of 4).
// One thread handles 4 co values: coords computed once, ~18 front-batched
// predicated LDG.128 for deep MLP, 4 select-tree reductions.

#define B_    4
#define CO_   16
#define PH_   7
#define PW_   7
#define H_    80
#define W_    80
#define SR_   2
#define C_    (CO_ * PH_ * PW_)     // 784
#define HW_   (H_ * W_)             // 6400
#define NROI  512
#define NBIN  (PH_ * PW_)           // 49
#define MPT   4                     // co values per thread
#define NTHR  (NROI * NBIN * MPT)   // 100352
#define TPB   128
#define MSTR  ((size_t)NBIN * HW_)  // plane stride per m step (floats)

__global__ __launch_bounds__(TPB, 5)
void psroi_align_kernel(const float* __restrict__ feat,
                        const float* __restrict__ rois,
                        float* __restrict__ out)
{
    const int t   = blockIdx.x * TPB + threadIdx.x;   // grid sized exactly
    const int g   = t & 3;                            // co group (co = 4g+m)
    const int q   = t >> 2;                           // n*49 + bin
    const int bin = q % NBIN;
    const int n   = q / NBIN;
    const int j   = bin % PW_;
    const int i   = bin / PW_;

    const float* __restrict__ r = rois + n * 5;
    const int   b  = (int)__ldg(r + 0);
    const float x1 = __ldg(r + 1) * (float)W_;
    const float y1 = __ldg(r + 2) * (float)H_;
    const float x2 = __ldg(r + 3) * (float)W_;
    const float y2 = __ldg(r + 4) * (float)H_;

    const float bin_h = fmaxf(y2 - y1, 0.1f) * (1.0f / (float)PH_);
    const float bin_w = fmaxf(x2 - x1, 0.1f) * (1.0f / (float)PW_);

    int   y0i[SR_], y1i[SR_], x0i[SR_], x1i[SR_];
    float hy[SR_], ly[SR_], hx[SR_], lx[SR_];

    #pragma unroll
    for (int s = 0; s < SR_; s++) {
        float ys = y1 + (float)i * bin_h + ((float)s + 0.5f) * bin_h * (1.0f / (float)SR_);
        bool ym = (ys >= -1.0f) && (ys <= (float)H_);
        float yc = fminf(fmaxf(ys, 0.0f), (float)(H_ - 1));
        float yf = floorf(yc);
        y0i[s] = (int)yf;
        y1i[s] = min(y0i[s] + 1, H_ - 1);
        ly[s]  = ym ? (yc - yf) : 0.0f;
        hy[s]  = ym ? (1.0f - (yc - yf)) : 0.0f;

        float xs = x1 + (float)j * bin_w + ((float)s + 0.5f) * bin_w * (1.0f / (float)SR_);
        bool xm = (xs >= -1.0f) && (xs <= (float)W_);
        float xc = fminf(fmaxf(xs, 0.0f), (float)(W_ - 1));
        float xf = floorf(xc);
        x0i[s] = (int)xf;
        x1i[s] = min(x0i[s] + 1, W_ - 1);
        lx[s]  = xm ? (xc - xf) : 0.0f;
        hx[s]  = xm ? (1.0f - (xc - xf)) : 0.0f;
    }

    // ---- column window: needed cols = [x0, x0+d3], d3 <= 3 ----
    const int c0 = x0i[0] & ~3;
    const int q0 = x0i[0] & 3;
    const int d1 = x1i[0] - x0i[0];      // 0..1
    const int d2 = x0i[1] - x0i[0];      // 0..2
    const int d3 = x1i[1] - x0i[0];      // 0..3

    const bool need_hi = (q0 + d3) >= 4; // if on, c0+7 <= 79 (in-bounds)

    const bool pb1  = (q0 & 1) != 0;
    const bool pb2  = (q0 & 2) != 0;
    const bool pd1  = d1 != 0;
    const bool pd2a = d2 >= 1;
    const bool pd2b = d2 == 2;
    const bool p3lo = (d3 & 1) != 0;
    const bool p3hi = (d3 & 2) != 0;

    // ---- rows: dedup duplicate y-rows ----
    const int dy  = y0i[1] - y0i[0];     // 0,1,2
    const bool ld2 = (dy == 2);
    const bool ld3 = (dy >= 1);
    const bool nh2 = need_hi && ld2;
    const bool nh3 = need_hi && ld3;

    const int c_m0 = (g * MPT) * NBIN + bin;   // channel for m=0
    const float* __restrict__ base =
        feat + ((size_t)b * C_ + c_m0) * HW_ + c0;

    const int ro0 = y0i[0] * W_;
    const int ro1 = y1i[0] * W_;
    const int ro2 = y0i[1] * W_;
    const int ro3 = y1i[1] * W_;

    const float wy0 = hy[0], wy1 = ly[0], wy2 = hy[1], wy3 = ly[1];
    const float hx0 = hx[0], lx0 = lx[0], hx1 = hx[1], lx1 = lx[1];

    float res[MPT];

    #pragma unroll
    for (int m = 0; m < MPT; m++) {
        const float* pm = base + (size_t)m * MSTR;
        const float4* a0 = (const float4*)(pm + ro0);
        const float4* a1 = (const float4*)(pm + ro1);
        const float4* a2 = (const float4*)(pm + ro2);
        const float4* a3 = (const float4*)(pm + ro3);

        // predicated front-batched loads (no branches)
        float4 lo0 = __ldg(a0);
        float4 lo1 = __ldg(a1);
        float4 lo2 = lo0, lo3 = lo1;
        float4 hi0 = make_float4(0.f, 0.f, 0.f, 0.f);
        float4 hi1 = hi0, hi2 = hi0, hi3 = hi0;

        if (ld2)     lo2 = __ldg(a2);
        if (ld3)     lo3 = __ldg(a3);
        if (need_hi) hi0 = __ldg(a0 + 1);
        if (need_hi) hi1 = __ldg(a1 + 1);
        if (nh2)     hi2 = __ldg(a2 + 1);
        if (nh3)     hi3 = __ldg(a3 + 1);

        if (!ld2) lo2 = ld3 ? lo1 : lo0;
        if (!ld3) lo3 = lo1;
        if (!ld2) hi2 = ld3 ? hi1 : hi0;
        if (!ld3) hi3 = hi1;

        const float4 LO[4] = { lo0, lo1, lo2, lo3 };
        const float4 HI[4] = { hi0, hi1, hi2, hi3 };
        const float  WY[4] = { wy0, wy1, wy2, wy3 };

        float sum = 0.0f;
        #pragma unroll
        for (int k = 0; k < 4; k++) {
            const float w0 = LO[k].x, w1 = LO[k].y, w2 = LO[k].z, w3 = LO[k].w;
            const float w4 = HI[k].x, w5 = HI[k].y, w6 = HI[k].z;

            const float t0 = pb1 ? w1 : w0;
            const float t1 = pb1 ? w2 : w1;
            const float t2 = pb1 ? w3 : w2;
            const float t3 = pb1 ? w4 : w3;
            const float t4 = pb1 ? w5 : w4;
            const float t5 = pb1 ? w6 : w5;
            const float s0 = pb2 ? t2 : t0;
            const float s1 = pb2 ? t3 : t1;
            const float s2 = pb2 ? t4 : t2;
            const float s3 = pb2 ? t5 : t3;

            const float v0 = s0;
            const float v1 = pd1 ? s1 : s0;
            const float v2 = pd2b ? s2 : (pd2a ? s1 : s0);
            const float u0 = p3lo ? s1 : s0;
            const float u1 = p3lo ? s3 : s2;
            const float v3 = p3hi ? u1 : u0;

            sum += WY[k] * ((hx0 * v0 + lx0 * v1) + (hx1 * v2 + lx1 * v3));
        }
        res[m] = sum * (1.0f / (float)(SR_ * SR_));
    }

    float* __restrict__ o = out + (size_t)n * C_ + c_m0;
    #pragma unroll
    for (int m = 0; m < MPT; m++)
        o[m * NBIN] = res[m];
}

extern "C" void kernel_launch(void* const* d_in, const int* in_sizes, int n_in,
                              void* d_out, int out_size)
{
    const float* feat = (const float*)d_in[0];
    const float* rois = (const float*)d_in[1];
    float* out        = (float*)d_out;

    psroi_align_kernel<<<NTHR / TPB, TPB>>>(feat, rois, out);
}